// round 10
// baseline (speedup 1.0000x reference)
#include <cuda_runtime.h>
#include <math.h>
#include <stdint.h>

// ---------------- geometry ----------------
#define W_    2048
#define HOUT  2046                 // VALID 3x3 output dim
#define NTOT  (W_ * W_)

// warp = 128 input cols (thread = 4 cols, float4), fixed 15 output rows/warp.
// Strips 0..15: cb=124*s, own outputs p in [1,125).  Strip 16: cb=1920
// (ends exactly at col 2048), owns p in [65,127).  All loads unconditional.
#define R_OUT  15
#define STRIPS 17
#define BANDS  137                 // ceil(2046/15)
#define NWARPS (STRIPS * BANDS)    // 2329
#define WPB    8
#define NBLOCKS ((NWARPS + WPB - 1) / WPB)  // 292 -> single wave @ 2/SM

// per-warp SMEM ring: DEPTH slots, one 128-col input row each:
//   [0..511]     E      (128 floats)
//   [512..1023]  v      (128 floats)
//   [1024..2559] strain (384 floats, gmem order)
#define DEPTH 4
#define SLOT_BYTES 2560
#define RING_BYTES (WPB * DEPTH * SLOT_BYTES)   // 81920

__device__ float g_bpart[3 * NBLOCKS];
__device__ unsigned int g_count;

#define CP_ASYNC16(dst, src) \
    asm volatile("cp.async.cg.shared.global [%0], [%1], 16;" :: "r"(dst), "l"(src) : "memory")
#define CP_COMMIT() asm volatile("cp.async.commit_group;" ::: "memory")
#define CP_WAIT(n)  asm volatile("cp.async.wait_group %0;" :: "n"(n) : "memory")

struct Row4 {
    float hE[4];    // horizontal 3-sum of E
    float hXX[4];   // horizontal 3-sum of sxx
    float hXY[4];   // horizontal 3-sum of sxy
    float dXY[4];   // sxy(j-1) - sxy(j+1)
    float dYY[4];   // syy(j-1) - syy(j+1)
};

__device__ __forceinline__ float warp_sum(float x) {
#pragma unroll
    for (int o = 16; o > 0; o >>= 1) x += __shfl_down_sync(0xffffffffu, x, o);
    return x;
}

// issue one 128-col row into a ring slot: 5 x 16B cp.async per thread
__device__ __forceinline__ void issue_row(
    uint32_t slot, int lane,
    const float* __restrict__ pE, const float* __restrict__ pv,
    const float* __restrict__ ps, int r, int cb)
{
    const int rr = (r < W_) ? r : (W_ - 1);       // clamp (last band only)
    const int base = rr * W_ + cb;
    CP_ASYNC16(slot + lane * 16,              pE + base + lane * 4);
    CP_ASYNC16(slot + 512 + lane * 16,        pv + base + lane * 4);
    const float* srcs = ps + 3 * base + lane * 12;
    CP_ASYNC16(slot + 1024 + lane * 48,       srcs);
    CP_ASYNC16(slot + 1024 + lane * 48 + 16,  srcs + 4);
    CP_ASYNC16(slot + 1024 + lane * 48 + 32,  srcs + 8);
    CP_COMMIT();
}

__device__ __forceinline__ void compute_row(
    const char* slot, int lane, Row4& o,
    bool ownrow, const bool* ownp, float& accE)
{
    const float4 E4 = *reinterpret_cast<const float4*>(slot + lane * 16);
    const float4 v4 = *reinterpret_cast<const float4*>(slot + 512 + lane * 16);
    const float4 sa = *reinterpret_cast<const float4*>(slot + 1024 + lane * 48);
    const float4 sb = *reinterpret_cast<const float4*>(slot + 1024 + lane * 48 + 16);
    const float4 sc = *reinterpret_cast<const float4*>(slot + 1024 + lane * 48 + 32);

    const float E[4]  = { E4.x, E4.y, E4.z, E4.w };
    const float v[4]  = { v4.x, v4.y, v4.z, v4.w };
    const float e0[4] = { sa.x, sa.w, sb.z, sc.y };
    const float e1[4] = { sa.y, sb.x, sb.w, sc.z };
    const float e2[4] = { sa.z, sb.y, sc.x, sc.w };

    float xx[4], yy[4], xy[4];
#pragma unroll
    for (int k = 0; k < 4; k++) {
        const float f = __fdividef(E[k], 1.0f - v[k] * v[k]);
        xx[k] = (e0[k] + v[k] * e1[k]) * f;
        yy[k] = (v[k] * e0[k] + e1[k]) * f;
        xy[k] = e2[k] * (1.0f - v[k]) * 0.5f * f;
    }

    // 8 shuffles per 128 cols; lane-edge garbage only feeds masked outputs
    const float El = __shfl_up_sync  (0xffffffffu, E[3],  1);
    const float Er = __shfl_down_sync(0xffffffffu, E[0],  1);
    const float xl = __shfl_up_sync  (0xffffffffu, xx[3], 1);
    const float xr = __shfl_down_sync(0xffffffffu, xx[0], 1);
    const float yl = __shfl_up_sync  (0xffffffffu, xy[3], 1);
    const float yr = __shfl_down_sync(0xffffffffu, xy[0], 1);
    const float sl = __shfl_up_sync  (0xffffffffu, yy[3], 1);
    const float sr = __shfl_down_sync(0xffffffffu, yy[0], 1);

    o.hE[0]  = El + E[0] + E[1];
    o.hE[1]  = E[0] + E[1] + E[2];
    o.hE[2]  = E[1] + E[2] + E[3];
    o.hE[3]  = E[2] + E[3] + Er;
    o.hXX[0] = xl + xx[0] + xx[1];
    o.hXX[1] = xx[0] + xx[1] + xx[2];
    o.hXX[2] = xx[1] + xx[2] + xx[3];
    o.hXX[3] = xx[2] + xx[3] + xr;
    o.hXY[0] = yl + xy[0] + xy[1];
    o.hXY[1] = xy[0] + xy[1] + xy[2];
    o.hXY[2] = xy[1] + xy[2] + xy[3];
    o.hXY[3] = xy[2] + xy[3] + yr;
    o.dXY[0] = yl - xy[1];
    o.dXY[1] = xy[0] - xy[2];
    o.dXY[2] = xy[1] - xy[3];
    o.dXY[3] = xy[2] - yr;
    o.dYY[0] = sl - yy[1];
    o.dYY[1] = yy[0] - yy[2];
    o.dYY[2] = yy[1] - yy[3];
    o.dYY[3] = yy[2] - sr;

    if (ownrow) {
#pragma unroll
        for (int k = 0; k < 4; k++)
            if (ownp[k]) accE += E[k];
    }
}

__global__ __launch_bounds__(256, 2)
void stress_loss_kernel(const float* __restrict__ pE,
                        const float* __restrict__ pv,
                        const float* __restrict__ ps,
                        float* __restrict__ out)
{
    extern __shared__ char ring_raw[];

    const int wl   = threadIdx.x >> 5;
    const int w    = blockIdx.x * WPB + wl;
    const int lane = threadIdx.x & 31;
    const int tid  = threadIdx.x;
    float accx = 0.f, accy = 0.f, accE = 0.f;

    if (w < NWARPS) {
        const int strip = w / BANDS;
        const int band  = w - strip * BANDS;
        const bool last_strip = (strip == STRIPS - 1);
        const int cb = last_strip ? (W_ - 128) : (124 * strip);
        const int r0 = band * R_OUT;
        const int p_lo = last_strip ? 65 : 1;     // output p in [p_lo, p_hi)
        const int p_hi = last_strip ? 127 : 125;
        const int q_lo = last_strip ? 64 : 0;     // accE col p in [q_lo, q_hi)
        const int q_hi = last_strip ? 128 : 124;
        const int own_hi_r = (band == BANDS - 1) ? W_ : r0 + R_OUT;

        bool okp[4], ownp[4];
#pragma unroll
        for (int k = 0; k < 4; k++) {
            const int p = lane * 4 + k;
            okp[k]  = (p >= p_lo) && (p < p_hi);
            ownp[k] = (p >= q_lo) && (p < q_hi);
        }

        char* wr = ring_raw + wl * (DEPTH * SLOT_BYTES);
        const uint32_t sb = (uint32_t)__cvta_generic_to_shared(wr);

        // ---- prologue: fill ring with rows r0..r0+3 ----
#pragma unroll
        for (int s = 0; s < DEPTH; s++)
            issue_row(sb + s * SLOT_BYTES, lane, pE, pv, ps, r0 + s, cb);

        Row4 A, B, C;
        CP_WAIT(2);
        compute_row(wr + 0 * SLOT_BYTES, lane, A, (r0     < own_hi_r), ownp, accE);
        compute_row(wr + 1 * SLOT_BYTES, lane, B, (r0 + 1 < own_hi_r), ownp, accE);

#pragma unroll
        for (int i = 0; i < R_OUT; i++) {
            issue_row(sb + (i & 3) * SLOT_BYTES, lane, pE, pv, ps, r0 + i + 4, cb);
            CP_WAIT(2);

            compute_row(wr + ((i + 2) & 3) * SLOT_BYTES, lane, C,
                        (r0 + i + 2 < own_hi_r), ownp, accE);

            const bool rowok = (r0 + i) < HOUT;   // output row validity
#pragma unroll
            for (int k = 0; k < 4; k++) {
                if (okp[k] && rowok) {
                    const float Ec = A.hE[k] + B.hE[k] + C.hE[k];
                    const float fx = C.hXX[k] - A.hXX[k]
                                   + (A.dXY[k] + B.dXY[k] + C.dXY[k]);
                    const float fy = (A.dYY[k] + B.dYY[k] + C.dYY[k])
                                   + C.hXY[k] - A.hXY[k];
                    const float inv = __fdividef(1.0f, Ec);
                    accx += fabsf(fx * inv);
                    accy += fabsf(fy * inv);
                }
            }
            A = B; B = C;   // renamed away by full unroll
        }
        CP_WAIT(0);
    }

    // ---- block reduction ----
    accx = warp_sum(accx);
    accy = warp_sum(accy);
    accE = warp_sum(accE);

    __shared__ float red[3][WPB];
    __shared__ int isLast;
    if (lane == 0) {
        red[0][wl] = accx;
        red[1][wl] = accy;
        red[2][wl] = accE;
    }
    __syncthreads();
    if (tid == 0) {
        float ax = 0.f, ay = 0.f, ae = 0.f;
#pragma unroll
        for (int q = 0; q < WPB; q++) { ax += red[0][q]; ay += red[1][q]; ae += red[2][q]; }
        g_bpart[blockIdx.x]               = ax;
        g_bpart[NBLOCKS + blockIdx.x]     = ay;
        g_bpart[2 * NBLOCKS + blockIdx.x] = ae;
        __threadfence();
        const unsigned int old = atomicAdd(&g_count, 1u);
        isLast = (old == NBLOCKS - 1);
    }
    __syncthreads();

    // ---- last block finalizes (fixed-order sum -> deterministic) ----
    if (isLast) {
        volatile const float* vp = (volatile const float*)g_bpart;
        double ax = 0.0, ay = 0.0, ae = 0.0;
        for (int i = tid; i < NBLOCKS; i += 256) {
            ax += (double)vp[i];
            ay += (double)vp[NBLOCKS + i];
            ae += (double)vp[2 * NBLOCKS + i];
        }
        __shared__ double sax[256], say[256], sae[256];
        sax[tid] = ax; say[tid] = ay; sae[tid] = ae;
        __syncthreads();
        for (int s = 128; s > 0; s >>= 1) {
            if (tid < s) { sax[tid] += sax[tid + s]; say[tid] += say[tid + s]; sae[tid] += sae[tid + s]; }
            __syncthreads();
        }
        if (tid == 0) {
            const double M = (double)HOUT * (double)HOUT;
            out[0] = (float)(sax[0] / M + say[0] / M
                             + fabs(sae[0] / (double)NTOT - 1.0) / 100.0);
            g_count = 0;   // reset for next graph replay
        }
    }
}

extern "C" void kernel_launch(void* const* d_in, const int* in_sizes, int n_in,
                              void* d_out, int out_size)
{
    const float* pred_E = (const float*)d_in[0];
    const float* pred_v = (const float*)d_in[1];
    const float* strain = (const float*)d_in[2];
    float* out = (float*)d_out;

    static int configured = 0;
    if (!configured) {
        cudaFuncSetAttribute(stress_loss_kernel,
                             cudaFuncAttributeMaxDynamicSharedMemorySize,
                             RING_BYTES);
        configured = 1;
    }

    stress_loss_kernel<<<NBLOCKS, 256, RING_BYTES>>>(pred_E, pred_v, strain, out);
}